// round 9
// baseline (speedup 1.0000x reference)
#include <cuda_runtime.h>
#include <cstdint>

// ============================================================
// BASE MoE layer (sm_103 plain-target: bf16 split-precision mma.sync)
// out[t] = x[t] + sigmoid(score)*( relu(LN_e(x) W1e^T + b1e) W2e^T + b2e )
// R9: replace tf32 m16n8k8 with bf16 m16n8k16 3-term split
//     (hi*hi + lo*hi + hi*lo). A pre-split & packed by producers;
//     B split in-kernel. Tests the "legacy tf32 HMMA is rate-limited"
//     hypothesis from R2..R8 invariance.
// ============================================================

#define TOKS 1024
#define DDIM 1024
#define FDIM 4096
#define NEXP 8
#define ROWS_PAD 1152
#define MAX_MT 16
#define KSPLIT 4
#define STAGES 3
#define ROWPAD 36                       // 32 words/floats + 4 pad
#define STAGE_FLOATS (128 * ROWPAD)     // 4608
#define SMEM_GEMM (2 * STAGES * STAGE_FLOATS * 4)   // 110,592 B
#define CTA_THREADS 128

// -------------------- device scratch --------------------
// A operands stored as packed bf16x2 words: word[2j]   = (hi(2j), hi(2j+1))
//                                           word[2j+1] = (lo(2j), lo(2j+1))
__device__ uint32_t g_xn[ROWS_PAD * DDIM];           // LN'd, sorted, split-packed
__device__ uint32_t g_H [ROWS_PAD * FDIM];           // FF1 out, split-packed
__device__ float    g_part[KSPLIT * ROWS_PAD * DDIM];// GEMM2 split-K partials
__device__ float g_mean[TOKS], g_rstd[TOKS], g_alpha[TOKS];
__device__ float g_alpha_s[TOKS];
__device__ int   g_eid[TOKS], g_eid_s[TOKS], g_tok[TOKS];
__device__ int   g_mt_e[MAX_MT], g_mt_r0[MAX_MT], g_mt_r1[MAX_MT];
__device__ int   g_num_mt;

// -------------------- PTX helpers --------------------
__device__ __forceinline__ void cp16(uint32_t dst, const void* src) {
    asm volatile("cp.async.cg.shared.global [%0], [%1], 16;" :: "r"(dst), "l"(src));
}
__device__ __forceinline__ void cp_commit() {
    asm volatile("cp.async.commit_group;" ::: "memory");
}
__device__ __forceinline__ void cp_wait1() {
    asm volatile("cp.async.wait_group 1;" ::: "memory");
}
// split (x0,x1) into packed bf16x2 hi word + lo word. lower 16 bits = x0.
__device__ __forceinline__ void split_pair(float x0, float x1,
                                           uint32_t& whi, uint32_t& wlo) {
    uint32_t h;
    asm("cvt.rn.bf16x2.f32 %0, %1, %2;" : "=r"(h) : "f"(x1), "f"(x0));
    float h0 = __uint_as_float(h << 16);
    float h1 = __uint_as_float(h & 0xffff0000u);
    uint32_t l;
    asm("cvt.rn.bf16x2.f32 %0, %1, %2;" : "=r"(l) : "f"(x1 - h1), "f"(x0 - h0));
    whi = h; wlo = l;
}
__device__ __forceinline__ void mma_bf16(float* c, const uint32_t* a, const uint32_t* b) {
    asm volatile(
        "mma.sync.aligned.m16n8k16.row.col.f32.bf16.bf16.f32 "
        "{%0,%1,%2,%3}, {%4,%5,%6,%7}, {%8,%9}, {%0,%1,%2,%3};"
        : "+f"(c[0]), "+f"(c[1]), "+f"(c[2]), "+f"(c[3])
        : "r"(a[0]), "r"(a[1]), "r"(a[2]), "r"(a[3]), "r"(b[0]), "r"(b[1]));
}

// -------------------- routing --------------------
__global__ void route_kernel(const float* __restrict__ x, const float* __restrict__ cent) {
    int t = blockIdx.x, tid = threadIdx.x;
    const float4* xr = (const float4*)(x + (size_t)t * DDIM);
    float sum = 0.f, sq = 0.f, acc[NEXP];
#pragma unroll
    for (int e = 0; e < NEXP; e++) acc[e] = 0.f;
    for (int i = tid; i < DDIM / 4; i += 128) {
        float4 xv = xr[i];
#pragma unroll
        for (int e = 0; e < NEXP; e++) {
            float4 cv = ((const float4*)cent)[e * (DDIM / 4) + i];
            acc[e] += xv.x * cv.x + xv.y * cv.y + xv.z * cv.z + xv.w * cv.w;
        }
        sum += xv.x + xv.y + xv.z + xv.w;
        sq  += xv.x * xv.x + xv.y * xv.y + xv.z * xv.z + xv.w * xv.w;
    }
#pragma unroll
    for (int o = 16; o > 0; o >>= 1) {
        sum += __shfl_xor_sync(0xffffffffu, sum, o);
        sq  += __shfl_xor_sync(0xffffffffu, sq,  o);
#pragma unroll
        for (int e = 0; e < NEXP; e++) acc[e] += __shfl_xor_sync(0xffffffffu, acc[e], o);
    }
    __shared__ float sh[4][NEXP + 2];
    int wid = tid >> 5, lid = tid & 31;
    if (lid == 0) {
        sh[wid][0] = sum; sh[wid][1] = sq;
#pragma unroll
        for (int e = 0; e < NEXP; e++) sh[wid][2 + e] = acc[e];
    }
    __syncthreads();
    if (tid == 0) {
        float s = 0.f, q = 0.f, a[NEXP];
#pragma unroll
        for (int e = 0; e < NEXP; e++) a[e] = 0.f;
        for (int w = 0; w < 4; w++) {
            s += sh[w][0]; q += sh[w][1];
#pragma unroll
            for (int e = 0; e < NEXP; e++) a[e] += sh[w][2 + e];
        }
        float mu  = s * (1.f / DDIM);
        float var = q * (1.f / DDIM) - mu * mu;
        g_mean[t] = mu;
        g_rstd[t] = rsqrtf(var + 1e-5f);
        int be = 0; float bs = a[0];
#pragma unroll
        for (int e = 1; e < NEXP; e++) if (a[e] > bs) { bs = a[e]; be = e; }
        g_eid[t]   = be;
        g_alpha[t] = 1.f / (1.f + expf(-bs));
    }
}

// -------------------- counting sort + m-tile descriptors --------------------
__global__ void sort_kernel() {
    __shared__ int cnt[NEXP], ctr[NEXP];
    int t = threadIdx.x;
    if (t < NEXP) cnt[t] = 0;
    __syncthreads();
    int e = g_eid[t];
    atomicAdd(&cnt[e], 1);
    __syncthreads();
    if (t == 0) {
        int o = 0, nm = 0;
        for (int k = 0; k < NEXP; k++) {
            ctr[k] = o;
            int c = cnt[k];
            for (int i = 0; i < c; i += 128) {
                g_mt_e[nm]  = k;
                g_mt_r0[nm] = o + i;
                g_mt_r1[nm] = o + ((i + 128 < c) ? (i + 128) : c);
                nm++;
            }
            o += c;
        }
        g_num_mt = nm;
    }
    __syncthreads();
    int pos = atomicAdd(&ctr[e], 1);
    g_tok[pos] = t;
    g_eid_s[pos] = e;
    g_alpha_s[pos] = g_alpha[t];
}

// -------------------- LN scatter (split-packed store) --------------------
__global__ void ln_kernel(const float* __restrict__ x, const float* __restrict__ gamma,
                          const float* __restrict__ beta) {
    int p = blockIdx.x, tid = threadIdx.x;
    int t = g_tok[p], e = g_eid_s[p];
    float mu = g_mean[t], rs = g_rstd[t];
    const float4* xr = (const float4*)(x + (size_t)t * DDIM);
    const float4* gr = (const float4*)(gamma + (size_t)e * DDIM);
    const float4* br = (const float4*)(beta + (size_t)e * DDIM);
    uint32_t* o = g_xn + (size_t)p * DDIM;
    for (int i = tid; i < DDIM / 4; i += 128) {
        float4 xv = xr[i], gv = gr[i], bv = br[i];
        float v0 = (xv.x - mu) * rs * gv.x + bv.x;
        float v1 = (xv.y - mu) * rs * gv.y + bv.y;
        float v2 = (xv.z - mu) * rs * gv.z + bv.z;
        float v3 = (xv.w - mu) * rs * gv.w + bv.w;
        uint4 w;
        split_pair(v0, v1, w.x, w.y);
        split_pair(v2, v3, w.z, w.w);
        *(uint4*)(o + 4 * i) = w;
    }
}

// -------------------- grouped GEMM (bf16 split, 64x64 warp tiles) --------
// A split-packed words (g_xn / g_H); W raw fp32 row-major [E][N][K], split in-kernel.
// MODE 1: g_H = relu(A W^T + b), split-packed store
// MODE 2: g_part[z] = partial(A W^T) over K chunk z (fp32)
template<int KCHUNK, int KFULL, int NDIM, int MODE>
__global__ void __launch_bounds__(CTA_THREADS, 2) gemm_mma(
    const uint32_t* __restrict__ A, const float* __restrict__ W,
    const float* __restrict__ bias, void* __restrict__ outv)
{
    int mt = blockIdx.y;
    if (mt >= g_num_mt) return;
    int e = g_mt_e[mt], row0 = g_mt_r0[mt], row1 = g_mt_r1[mt];
    int n0 = blockIdx.x * 128;
    int bz = blockIdx.z;
    int k0 = bz * KCHUNK;

    extern __shared__ float sh[];
    float* shB = sh + STAGES * STAGE_FLOATS;
    uint32_t sA, sB;
    {
        uint32_t base;
        asm("{ .reg .u64 t; cvta.to.shared.u64 t, %1; cvt.u32.u64 %0, t; }"
            : "=r"(base) : "l"(sh));
        sA = base;
        sB = base + STAGES * STAGE_FLOATS * 4;
    }

    int tid = threadIdx.x;
    int lane = tid & 31, wid = tid >> 5;      // 4 warps
    int wm = wid >> 1, wn = wid & 1;          // 2 x 2 warp grid, 64x64 tiles
    int lg = lane >> 2, lt = lane & 3;

    const int KT = KCHUNK / 32;

    float acc[4][8][4];                        // 128 registers
#pragma unroll
    for (int a = 0; a < 4; a++)
#pragma unroll
        for (int b = 0; b < 8; b++)
#pragma unroll
            for (int c = 0; c < 4; c++) acc[a][b][c] = 0.f;

    const uint32_t* Abase = A + (size_t)row0 * KFULL + k0;
    const float*    Wbase = W + ((size_t)e * NDIM + n0) * KFULL + k0;

    auto load_stage = [&](int it, int s) {
        if (it < KT) {
            int kk0 = it * 32;
            uint32_t dA = sA + s * (STAGE_FLOATS * 4);
            uint32_t dB = sB + s * (STAGE_FLOATS * 4);
#pragma unroll
            for (int i = 0; i < 8; i++) {
                int chunk = tid + i * CTA_THREADS;
                int r = chunk >> 3, c = chunk & 7;
                cp16(dA + r * (ROWPAD * 4) + c * 16, Abase + (size_t)r * KFULL + kk0 + c * 4);
            }
#pragma unroll
            for (int i = 0; i < 8; i++) {
                int chunk = tid + i * CTA_THREADS;
                int r = chunk >> 3, c = chunk & 7;
                cp16(dB + r * (ROWPAD * 4) + c * 16, Wbase + (size_t)r * KFULL + kk0 + c * 4);
            }
        }
        cp_commit();
    };

    load_stage(0, 0);
    load_stage(1, 1);

    for (int it = 0; it < KT; it++) {
        cp_wait1();
        __syncthreads();
        load_stage(it + 2, (it + 2) % STAGES);

        int s = it % STAGES;
        const uint32_t* As = (const uint32_t*)(sh + s * STAGE_FLOATS);
        const float*    Bs = shB + s * STAGE_FLOATS;

        // two k16 chunks per 32-k iter
#pragma unroll
        for (int c16 = 0; c16 < 2; c16++) {
            // A fragments: hi/lo interleaved words
            uint32_t ah[4][4], al[4][4];
#pragma unroll
            for (int m = 0; m < 4; m++) {
                const uint32_t* ap = As + (wm * 64 + m * 16 + lg) * ROWPAD + c16 * 16 + 2 * lt;
                uint2 p0 = *(const uint2*)ap;                       // row lg,   j=lt
                uint2 p1 = *(const uint2*)(ap + 8 * ROWPAD);        // row lg+8, j=lt
                uint2 p2 = *(const uint2*)(ap + 8);                 // row lg,   j=lt+4
                uint2 p3 = *(const uint2*)(ap + 8 * ROWPAD + 8);    // row lg+8, j=lt+4
                ah[m][0] = p0.x; al[m][0] = p0.y;
                ah[m][1] = p1.x; al[m][1] = p1.y;
                ah[m][2] = p2.x; al[m][2] = p2.y;
                ah[m][3] = p3.x; al[m][3] = p3.y;
            }
#pragma unroll
            for (int n = 0; n < 8; n++) {
                // B fragment: load fp32 pair, split to (hi, lo) packed words
                const float* bp = Bs + (wn * 64 + n * 8 + lg) * ROWPAD + c16 * 16 + 2 * lt;
                float2 q0 = *(const float2*)bp;          // k = 2lt, 2lt+1
                float2 q1 = *(const float2*)(bp + 8);    // k = 2lt+8, 2lt+9
                uint32_t bh[2], bl[2];
                split_pair(q0.x, q0.y, bh[0], bl[0]);
                split_pair(q1.x, q1.y, bh[1], bl[1]);
                // 3-term split product; dependents spaced by m-loop (4 chains)
#pragma unroll
                for (int m = 0; m < 4; m++) mma_bf16(acc[m][n], ah[m], bh);
#pragma unroll
                for (int m = 0; m < 4; m++) mma_bf16(acc[m][n], al[m], bh);
#pragma unroll
                for (int m = 0; m < 4; m++) mma_bf16(acc[m][n], ah[m], bl);
            }
        }
    }

    // -------------------- epilogue --------------------
#pragma unroll
    for (int m = 0; m < 4; m++) {
#pragma unroll
        for (int half = 0; half < 2; half++) {
            int r = wm * 64 + m * 16 + half * 8 + lg;
            int p = row0 + r;
            if (p >= row1) continue;
            if (MODE == 1) {
                // relu + bias, split-packed store into g_H
                uint32_t* dst = (uint32_t*)outv + (size_t)p * NDIM + n0;
                const float* bs = bias + (size_t)e * NDIM + n0;
#pragma unroll
                for (int n = 0; n < 8; n++) {
                    int col8 = wn * 64 + n * 8;
                    float v0 = fmaxf(acc[m][n][half * 2 + 0] + bs[col8 + 2 * lt],     0.f);
                    float v1 = fmaxf(acc[m][n][half * 2 + 1] + bs[col8 + 2 * lt + 1], 0.f);
                    uint2 w;
                    split_pair(v0, v1, w.x, w.y);
                    *(uint2*)(dst + col8 + 2 * lt) = w;
                }
            } else {
                // raw fp32 partial store into this K-chunk's slab
                float* dst = (float*)outv + ((size_t)bz * ROWS_PAD + p) * NDIM + n0;
#pragma unroll
                for (int n = 0; n < 8; n++) {
                    int col = wn * 64 + n * 8 + 2 * lt;
                    float2 o;
                    o.x = acc[m][n][half * 2 + 0];
                    o.y = acc[m][n][half * 2 + 1];
                    *(float2*)(dst + col) = o;
                }
            }
        }
    }
}

// -------------------- split-K combine + gated residual --------------------
__global__ void combine_kernel(const float* __restrict__ x, const float* __restrict__ b2,
                               float* __restrict__ out) {
    int p = blockIdx.x, tid = threadIdx.x;
    int t = g_tok[p], e = g_eid_s[p];
    float al = g_alpha_s[p];
    const float4* xr = (const float4*)(x + (size_t)t * DDIM);
    const float4* bs = (const float4*)(b2 + (size_t)e * DDIM);
    float4* dst = (float4*)(out + (size_t)t * DDIM);
    for (int i = tid; i < DDIM / 4; i += 128) {
        float4 s = ((const float4*)(g_part + (size_t)p * DDIM))[i];
#pragma unroll
        for (int z = 1; z < KSPLIT; z++) {
            float4 v = ((const float4*)(g_part + ((size_t)z * ROWS_PAD + p) * DDIM))[i];
            s.x += v.x; s.y += v.y; s.z += v.z; s.w += v.w;
        }
        float4 xv = xr[i], bv = bs[i], o;
        o.x = xv.x + al * (s.x + bv.x);
        o.y = xv.y + al * (s.y + bv.y);
        o.z = xv.z + al * (s.z + bv.z);
        o.w = xv.w + al * (s.w + bv.w);
        dst[i] = o;
    }
}

// -------------------- host --------------------
extern "C" void kernel_launch(void* const* d_in, const int* in_sizes, int n_in,
                              void* d_out, int out_size) {
    const float* x     = (const float*)d_in[0];
    const float* cent  = (const float*)d_in[1];
    const float* gamma = (const float*)d_in[2];
    const float* beta  = (const float*)d_in[3];
    const float* W1    = (const float*)d_in[4];
    const float* b1    = (const float*)d_in[5];
    const float* W2    = (const float*)d_in[6];
    const float* b2    = (const float*)d_in[7];
    float* out = (float*)d_out;

    void* pxn = nullptr; void* pH = nullptr; void* ppart = nullptr;
    cudaGetSymbolAddress(&pxn, g_xn);
    cudaGetSymbolAddress(&pH,  g_H);
    cudaGetSymbolAddress(&ppart, g_part);

    cudaFuncSetAttribute((const void*)gemm_mma<DDIM, DDIM, FDIM, 1>,
                         cudaFuncAttributeMaxDynamicSharedMemorySize, SMEM_GEMM);
    cudaFuncSetAttribute((const void*)gemm_mma<FDIM / KSPLIT, FDIM, DDIM, 2>,
                         cudaFuncAttributeMaxDynamicSharedMemorySize, SMEM_GEMM);

    route_kernel<<<TOKS, 128>>>(x, cent);
    sort_kernel<<<1, TOKS>>>();
    ln_kernel<<<TOKS, 128>>>(x, gamma, beta);
    gemm_mma<DDIM, DDIM, FDIM, 1><<<dim3(FDIM / 128, MAX_MT, 1), CTA_THREADS, SMEM_GEMM>>>(
        (const uint32_t*)pxn, W1, b1, pH);
    gemm_mma<FDIM / KSPLIT, FDIM, DDIM, 2><<<dim3(DDIM / 128, MAX_MT, KSPLIT), CTA_THREADS, SMEM_GEMM>>>(
        (const uint32_t*)pH, W2, nullptr, ppart);
    combine_kernel<<<TOKS, 128>>>(x, b2, out);
}

// round 10
// speedup vs baseline: 1.9679x; 1.9679x over previous
#include <cuda_runtime.h>
#include <cstdint>

// ============================================================
// BASE MoE layer (sm_103 plain-target: fp16 m16n8k16 mma.sync, fp32 accum)
// out[t] = x[t] + sigmoid(score)*( relu(LN_e(x) W1e^T + b1e) W2e^T + b2e )
// R10: legacy HMMA on sm_103 is per-INSTRUCTION rate-limited (~24cyc
//      regardless of kind/K, proven R8 vs R9). So minimize instructions:
//      fp16 k16 single-term = half of tf32's instruction count.
//      fp16 mantissa (11b) == tf32 mantissa -> same accuracy class.
// ============================================================

#define TOKS 1024
#define DDIM 1024
#define FDIM 4096
#define NEXP 8
#define ROWS_PAD 1152
#define MAX_MT 16
#define KSPLIT 4
#define STAGES 3
#define ROWPAD 36                         // B: 32 floats + 4 pad
#define PADA 24                           // A: 16 words + 8 pad (stride 24 mod 32 -> conflict-free)
#define STAGE_B_FLOATS (128 * ROWPAD)     // 4608 floats = 18432 B
#define STAGE_A_WORDS  (128 * PADA)       // 3072 words  = 12288 B
#define SMEM_GEMM (STAGES * (STAGE_A_WORDS * 4 + STAGE_B_FLOATS * 4))  // 92160 B
#define CTA_THREADS 128

// -------------------- device scratch --------------------
// A operands: packed fp16x2 words, permuted [0,4,1,5,2,6,3,7] per 8-word group
__device__ uint32_t g_xn[ROWS_PAD * DDIM / 2];
__device__ uint32_t g_H [ROWS_PAD * FDIM / 2];
__device__ float    g_part[KSPLIT * ROWS_PAD * DDIM];
__device__ float g_mean[TOKS], g_rstd[TOKS], g_alpha[TOKS];
__device__ float g_alpha_s[TOKS];
__device__ int   g_eid[TOKS], g_eid_s[TOKS], g_tok[TOKS];
__device__ int   g_mt_e[MAX_MT], g_mt_r0[MAX_MT], g_mt_r1[MAX_MT];
__device__ int   g_num_mt;

// -------------------- PTX helpers --------------------
__device__ __forceinline__ void cp16(uint32_t dst, const void* src) {
    asm volatile("cp.async.cg.shared.global [%0], [%1], 16;" :: "r"(dst), "l"(src));
}
__device__ __forceinline__ void cp_commit() {
    asm volatile("cp.async.commit_group;" ::: "memory");
}
__device__ __forceinline__ void cp_wait1() {
    asm volatile("cp.async.wait_group 1;" ::: "memory");
}
// pack (lo, hi) floats -> fp16x2 word (lower 16 bits = lo)
__device__ __forceinline__ uint32_t pack_f16(float lo, float hi) {
    uint32_t r;
    asm("cvt.rn.f16x2.f32 %0, %1, %2;" : "=r"(r) : "f"(hi), "f"(lo));
    return r;
}
__device__ __forceinline__ void mma_f16(float* c, const uint32_t* a, const uint32_t* b) {
    asm volatile(
        "mma.sync.aligned.m16n8k16.row.col.f32.f16.f16.f32 "
        "{%0,%1,%2,%3}, {%4,%5,%6,%7}, {%8,%9}, {%0,%1,%2,%3};"
        : "+f"(c[0]), "+f"(c[1]), "+f"(c[2]), "+f"(c[3])
        : "r"(a[0]), "r"(a[1]), "r"(a[2]), "r"(a[3]), "r"(b[0]), "r"(b[1]));
}
// permuted position of logical word j within its 8-word group: [0,4,1,5,2,6,3,7]
__device__ __forceinline__ int pidx(int j) { return ((j & 3) << 1) | ((j & 4) >> 2); }

// -------------------- routing --------------------
__global__ void route_kernel(const float* __restrict__ x, const float* __restrict__ cent) {
    int t = blockIdx.x, tid = threadIdx.x;
    const float4* xr = (const float4*)(x + (size_t)t * DDIM);
    float sum = 0.f, sq = 0.f, acc[NEXP];
#pragma unroll
    for (int e = 0; e < NEXP; e++) acc[e] = 0.f;
    for (int i = tid; i < DDIM / 4; i += 128) {
        float4 xv = xr[i];
#pragma unroll
        for (int e = 0; e < NEXP; e++) {
            float4 cv = ((const float4*)cent)[e * (DDIM / 4) + i];
            acc[e] += xv.x * cv.x + xv.y * cv.y + xv.z * cv.z + xv.w * cv.w;
        }
        sum += xv.x + xv.y + xv.z + xv.w;
        sq  += xv.x * xv.x + xv.y * xv.y + xv.z * xv.z + xv.w * xv.w;
    }
#pragma unroll
    for (int o = 16; o > 0; o >>= 1) {
        sum += __shfl_xor_sync(0xffffffffu, sum, o);
        sq  += __shfl_xor_sync(0xffffffffu, sq,  o);
#pragma unroll
        for (int e = 0; e < NEXP; e++) acc[e] += __shfl_xor_sync(0xffffffffu, acc[e], o);
    }
    __shared__ float sh[4][NEXP + 2];
    int wid = tid >> 5, lid = tid & 31;
    if (lid == 0) {
        sh[wid][0] = sum; sh[wid][1] = sq;
#pragma unroll
        for (int e = 0; e < NEXP; e++) sh[wid][2 + e] = acc[e];
    }
    __syncthreads();
    if (tid == 0) {
        float s = 0.f, q = 0.f, a[NEXP];
#pragma unroll
        for (int e = 0; e < NEXP; e++) a[e] = 0.f;
        for (int w = 0; w < 4; w++) {
            s += sh[w][0]; q += sh[w][1];
#pragma unroll
            for (int e = 0; e < NEXP; e++) a[e] += sh[w][2 + e];
        }
        float mu  = s * (1.f / DDIM);
        float var = q * (1.f / DDIM) - mu * mu;
        g_mean[t] = mu;
        g_rstd[t] = rsqrtf(var + 1e-5f);
        int be = 0; float bs = a[0];
#pragma unroll
        for (int e = 1; e < NEXP; e++) if (a[e] > bs) { bs = a[e]; be = e; }
        g_eid[t]   = be;
        g_alpha[t] = 1.f / (1.f + expf(-bs));
    }
}

// -------------------- counting sort + m-tile descriptors --------------------
__global__ void sort_kernel() {
    __shared__ int cnt[NEXP], ctr[NEXP];
    int t = threadIdx.x;
    if (t < NEXP) cnt[t] = 0;
    __syncthreads();
    int e = g_eid[t];
    atomicAdd(&cnt[e], 1);
    __syncthreads();
    if (t == 0) {
        int o = 0, nm = 0;
        for (int k = 0; k < NEXP; k++) {
            ctr[k] = o;
            int c = cnt[k];
            for (int i = 0; i < c; i += 128) {
                g_mt_e[nm]  = k;
                g_mt_r0[nm] = o + i;
                g_mt_r1[nm] = o + ((i + 128 < c) ? (i + 128) : c);
                nm++;
            }
            o += c;
        }
        g_num_mt = nm;
    }
    __syncthreads();
    int pos = atomicAdd(&ctr[e], 1);
    g_tok[pos] = t;
    g_eid_s[pos] = e;
    g_alpha_s[pos] = g_alpha[t];
}

// -------------------- LN scatter (fp16-packed, word-permuted) ----------------
__global__ void ln_kernel(const float* __restrict__ x, const float* __restrict__ gamma,
                          const float* __restrict__ beta) {
    int p = blockIdx.x, tid = threadIdx.x;
    int t = g_tok[p], e = g_eid_s[p];
    float mu = g_mean[t], rs = g_rstd[t];
    const float4* xr = (const float4*)(x + (size_t)t * DDIM);
    const float4* gr = (const float4*)(gamma + (size_t)e * DDIM);
    const float4* br = (const float4*)(beta + (size_t)e * DDIM);
    uint32_t* o = g_xn + (size_t)p * (DDIM / 2);
    for (int i = tid; i < DDIM / 4; i += 128) {
        float4 xv = xr[i], gv = gr[i], bv = br[i];
        float v0 = (xv.x - mu) * rs * gv.x + bv.x;
        float v1 = (xv.y - mu) * rs * gv.y + bv.y;
        float v2 = (xv.z - mu) * rs * gv.z + bv.z;
        float v3 = (xv.w - mu) * rs * gv.w + bv.w;
        int w0 = 2 * i, w1 = 2 * i + 1;
        int base = w0 & ~7;
        o[base + pidx(w0 & 7)] = pack_f16(v0, v1);
        o[base + pidx(w1 & 7)] = pack_f16(v2, v3);
    }
}

// -------------------- grouped GEMM (fp16 k16, 64x64 warp tiles) -----------
// A fp16-packed permuted words (g_xn / g_H); W raw fp32 [E][N][K], cvt in-kernel.
// MODE 1: g_H = relu(A W^T + b), fp16-packed permuted store
// MODE 2: g_part[z] = partial(A W^T) over K chunk z (fp32)
template<int KCHUNK, int KFULL, int NDIM, int MODE>
__global__ void __launch_bounds__(CTA_THREADS, 2) gemm_mma(
    const uint32_t* __restrict__ A, const float* __restrict__ W,
    const float* __restrict__ bias, void* __restrict__ outv)
{
    int mt = blockIdx.y;
    if (mt >= g_num_mt) return;
    int e = g_mt_e[mt], row0 = g_mt_r0[mt], row1 = g_mt_r1[mt];
    int n0 = blockIdx.x * 128;
    int bz = blockIdx.z;
    const int KW = KFULL / 2;            // A row stride in words
    int k0w = bz * (KCHUNK / 2);

    extern __shared__ float sh[];
    uint32_t sA, sB;
    {
        uint32_t base;
        asm("{ .reg .u64 t; cvta.to.shared.u64 t, %1; cvt.u32.u64 %0, t; }"
            : "=r"(base) : "l"(sh));
        sA = base;
        sB = base + STAGES * (STAGE_A_WORDS * 4);
    }
    const uint32_t* shA = (const uint32_t*)sh;
    const float* shB = sh + STAGES * STAGE_A_WORDS;   // B floats after A words

    int tid = threadIdx.x;
    int lane = tid & 31, wid = tid >> 5;      // 4 warps
    int wm = wid >> 1, wn = wid & 1;          // 2 x 2 warp grid, 64x64 tiles
    int lg = lane >> 2, lt = lane & 3;

    const int KT = KCHUNK / 32;

    float acc[4][8][4];                        // 128 registers
#pragma unroll
    for (int a = 0; a < 4; a++)
#pragma unroll
        for (int b = 0; b < 8; b++)
#pragma unroll
            for (int c = 0; c < 4; c++) acc[a][b][c] = 0.f;

    const uint32_t* Abase = A + (size_t)row0 * KW + k0w;
    const float*    Wbase = W + ((size_t)e * NDIM + n0) * KFULL + bz * KCHUNK;

    auto load_stage = [&](int it, int s) {
        if (it < KT) {
            int kk0w = it * 16;                 // 32 k = 16 words
            uint32_t dA = sA + s * (STAGE_A_WORDS * 4);
            uint32_t dB = sB + s * (STAGE_B_FLOATS * 4);
            // A: 128 rows x 16 words = 512 16B-chunks
#pragma unroll
            for (int i = 0; i < 4; i++) {
                int chunk = tid + i * CTA_THREADS;
                int r = chunk >> 2, c = chunk & 3;
                cp16(dA + r * (PADA * 4) + c * 16, Abase + (size_t)r * KW + kk0w + c * 4);
            }
            // B: 128 rows x 32 floats = 1024 16B-chunks
#pragma unroll
            for (int i = 0; i < 8; i++) {
                int chunk = tid + i * CTA_THREADS;
                int r = chunk >> 3, c = chunk & 7;
                cp16(dB + r * (ROWPAD * 4) + c * 16,
                     Wbase + (size_t)r * KFULL + it * 32 + c * 4);
            }
        }
        cp_commit();
    };

    load_stage(0, 0);
    load_stage(1, 1);

    for (int it = 0; it < KT; it++) {
        cp_wait1();
        __syncthreads();
        load_stage(it + 2, (it + 2) % STAGES);

        int s = it % STAGES;
        const uint32_t* As = shA + s * STAGE_A_WORDS;
        const float*    Bs = shB + s * STAGE_B_FLOATS;

        // two k16 chunks per 32-k iter
#pragma unroll
        for (int c16 = 0; c16 < 2; c16++) {
            uint32_t afr[4][4];
#pragma unroll
            for (int m = 0; m < 4; m++) {
                // permuted: pair at 2*lt = logical words (lt, lt+4) = a0,a2
                const uint32_t* ap = As + (wm * 64 + m * 16 + lg) * PADA + c16 * 8 + 2 * lt;
                uint2 p0 = *(const uint2*)ap;                 // row lg
                uint2 p1 = *(const uint2*)(ap + 8 * PADA);    // row lg+8
                afr[m][0] = p0.x; afr[m][2] = p0.y;
                afr[m][1] = p1.x; afr[m][3] = p1.y;
            }
#pragma unroll
            for (int n = 0; n < 8; n++) {
                const float* bp = Bs + (wn * 64 + n * 8 + lg) * ROWPAD + c16 * 16 + 2 * lt;
                float2 q0 = *(const float2*)bp;          // k = 2lt, 2lt+1
                float2 q1 = *(const float2*)(bp + 8);    // k = 2lt+8, 2lt+9
                uint32_t bfr[2];
                bfr[0] = pack_f16(q0.x, q0.y);
                bfr[1] = pack_f16(q1.x, q1.y);
#pragma unroll
                for (int m = 0; m < 4; m++)
                    mma_f16(acc[m][n], afr[m], bfr);
            }
        }
    }

    // -------------------- epilogue --------------------
#pragma unroll
    for (int m = 0; m < 4; m++) {
#pragma unroll
        for (int half = 0; half < 2; half++) {
            int r = wm * 64 + m * 16 + half * 8 + lg;
            int p = row0 + r;
            if (p >= row1) continue;
            if (MODE == 1) {
                // relu + bias, fp16-pack, word-permuted store into g_H
                uint32_t* dst = (uint32_t*)outv + (size_t)p * (NDIM / 2) + n0 / 2;
                const float* bs = bias + (size_t)e * NDIM + n0;
#pragma unroll
                for (int n = 0; n < 8; n++) {
                    int col8 = wn * 64 + n * 8;
                    float v0 = fmaxf(acc[m][n][half * 2 + 0] + bs[col8 + 2 * lt],     0.f);
                    float v1 = fmaxf(acc[m][n][half * 2 + 1] + bs[col8 + 2 * lt + 1], 0.f);
                    int lw = (col8 >> 1) + lt;          // local word index 0..63
                    dst[(lw & ~7) + pidx(lw & 7)] = pack_f16(v0, v1);
                }
            } else {
                // raw fp32 partial store into this K-chunk's slab
                float* dst = (float*)outv + ((size_t)bz * ROWS_PAD + p) * NDIM + n0;
#pragma unroll
                for (int n = 0; n < 8; n++) {
                    int col = wn * 64 + n * 8 + 2 * lt;
                    float2 o;
                    o.x = acc[m][n][half * 2 + 0];
                    o.y = acc[m][n][half * 2 + 1];
                    *(float2*)(dst + col) = o;
                }
            }
        }
    }
}

// -------------------- split-K combine + gated residual --------------------
__global__ void combine_kernel(const float* __restrict__ x, const float* __restrict__ b2,
                               float* __restrict__ out) {
    int p = blockIdx.x, tid = threadIdx.x;
    int t = g_tok[p], e = g_eid_s[p];
    float al = g_alpha_s[p];
    const float4* xr = (const float4*)(x + (size_t)t * DDIM);
    const float4* bs = (const float4*)(b2 + (size_t)e * DDIM);
    float4* dst = (float4*)(out + (size_t)t * DDIM);
    for (int i = tid; i < DDIM / 4; i += 128) {
        float4 s = ((const float4*)(g_part + (size_t)p * DDIM))[i];
#pragma unroll
        for (int z = 1; z < KSPLIT; z++) {
            float4 v = ((const float4*)(g_part + ((size_t)z * ROWS_PAD + p) * DDIM))[i];
            s.x += v.x; s.y += v.y; s.z += v.z; s.w += v.w;
        }
        float4 xv = xr[i], bv = bs[i], o;
        o.x = xv.x + al * (s.x + bv.x);
        o.y = xv.y + al * (s.y + bv.y);
        o.z = xv.z + al * (s.z + bv.z);
        o.w = xv.w + al * (s.w + bv.w);
        dst[i] = o;
    }
}

// -------------------- host --------------------
extern "C" void kernel_launch(void* const* d_in, const int* in_sizes, int n_in,
                              void* d_out, int out_size) {
    const float* x     = (const float*)d_in[0];
    const float* cent  = (const float*)d_in[1];
    const float* gamma = (const float*)d_in[2];
    const float* beta  = (const float*)d_in[3];
    const float* W1    = (const float*)d_in[4];
    const float* b1    = (const float*)d_in[5];
    const float* W2    = (const float*)d_in[6];
    const float* b2    = (const float*)d_in[7];
    float* out = (float*)d_out;

    void* pxn = nullptr; void* pH = nullptr; void* ppart = nullptr;
    cudaGetSymbolAddress(&pxn, g_xn);
    cudaGetSymbolAddress(&pH,  g_H);
    cudaGetSymbolAddress(&ppart, g_part);

    cudaFuncSetAttribute((const void*)gemm_mma<DDIM, DDIM, FDIM, 1>,
                         cudaFuncAttributeMaxDynamicSharedMemorySize, SMEM_GEMM);
    cudaFuncSetAttribute((const void*)gemm_mma<FDIM / KSPLIT, FDIM, DDIM, 2>,
                         cudaFuncAttributeMaxDynamicSharedMemorySize, SMEM_GEMM);

    route_kernel<<<TOKS, 128>>>(x, cent);
    sort_kernel<<<1, TOKS>>>();
    ln_kernel<<<TOKS, 128>>>(x, gamma, beta);
    gemm_mma<DDIM, DDIM, FDIM, 1><<<dim3(FDIM / 128, MAX_MT, 1), CTA_THREADS, SMEM_GEMM>>>(
        (const uint32_t*)pxn, W1, b1, pH);
    gemm_mma<FDIM / KSPLIT, FDIM, DDIM, 2><<<dim3(DDIM / 128, MAX_MT, KSPLIT), CTA_THREADS, SMEM_GEMM>>>(
        (const uint32_t*)pH, W2, nullptr, ppart);
    combine_kernel<<<TOKS, 128>>>(x, b2, out);
}

// round 11
// speedup vs baseline: 2.2468x; 1.1417x over previous
#include <cuda_runtime.h>
#include <cstdint>

// ============================================================
// BASE MoE layer (sm_103 plain-target: fp16 m16n8k16 mma.sync, fp32 accum)
// out[t] = x[t] + sigmoid(score)*( relu(LN_e(x) W1e^T + b1e) W2e^T + b2e )
// R11: fp16 k16 (R10's halved instruction count) x 16 warps/SM
//      (R4's proven issue-sustaining occupancy): 256-thread CTAs,
//      2x4 warp grid, 64x32 warp tiles, 2 CTAs/SM.
// ============================================================

#define TOKS 1024
#define DDIM 1024
#define FDIM 4096
#define NEXP 8
#define ROWS_PAD 1152
#define MAX_MT 16
#define KSPLIT 4
#define STAGES 3
#define ROWPAD 36                         // B: 32 floats + 4 pad
#define PADA 24                           // A: 16 words + 8 pad (conflict-free LDS.64)
#define STAGE_B_FLOATS (128 * ROWPAD)     // 4608 floats = 18432 B
#define STAGE_A_WORDS  (128 * PADA)       // 3072 words  = 12288 B
#define SMEM_GEMM (STAGES * (STAGE_A_WORDS * 4 + STAGE_B_FLOATS * 4))  // 92160 B
#define CTA_THREADS 256

// -------------------- device scratch --------------------
// A operands: packed fp16x2 words, permuted [0,4,1,5,2,6,3,7] per 8-word group
__device__ uint32_t g_xn[ROWS_PAD * DDIM / 2];
__device__ uint32_t g_H [ROWS_PAD * FDIM / 2];
__device__ float    g_part[KSPLIT * ROWS_PAD * DDIM];
__device__ float g_mean[TOKS], g_rstd[TOKS], g_alpha[TOKS];
__device__ float g_alpha_s[TOKS];
__device__ int   g_eid[TOKS], g_eid_s[TOKS], g_tok[TOKS];
__device__ int   g_mt_e[MAX_MT], g_mt_r0[MAX_MT], g_mt_r1[MAX_MT];
__device__ int   g_num_mt;

// -------------------- PTX helpers --------------------
__device__ __forceinline__ void cp16(uint32_t dst, const void* src) {
    asm volatile("cp.async.cg.shared.global [%0], [%1], 16;" :: "r"(dst), "l"(src));
}
__device__ __forceinline__ void cp_commit() {
    asm volatile("cp.async.commit_group;" ::: "memory");
}
__device__ __forceinline__ void cp_wait1() {
    asm volatile("cp.async.wait_group 1;" ::: "memory");
}
// pack (lo, hi) floats -> fp16x2 word (lower 16 bits = lo)
__device__ __forceinline__ uint32_t pack_f16(float lo, float hi) {
    uint32_t r;
    asm("cvt.rn.f16x2.f32 %0, %1, %2;" : "=r"(r) : "f"(hi), "f"(lo));
    return r;
}
__device__ __forceinline__ void mma_f16(float* c, const uint32_t* a, const uint32_t* b) {
    asm volatile(
        "mma.sync.aligned.m16n8k16.row.col.f32.f16.f16.f32 "
        "{%0,%1,%2,%3}, {%4,%5,%6,%7}, {%8,%9}, {%0,%1,%2,%3};"
        : "+f"(c[0]), "+f"(c[1]), "+f"(c[2]), "+f"(c[3])
        : "r"(a[0]), "r"(a[1]), "r"(a[2]), "r"(a[3]), "r"(b[0]), "r"(b[1]));
}
// permuted position of logical word j within its 8-word group: [0,4,1,5,2,6,3,7]
__device__ __forceinline__ int pidx(int j) { return ((j & 3) << 1) | ((j & 4) >> 2); }

// -------------------- routing --------------------
__global__ void route_kernel(const float* __restrict__ x, const float* __restrict__ cent) {
    int t = blockIdx.x, tid = threadIdx.x;
    const float4* xr = (const float4*)(x + (size_t)t * DDIM);
    float sum = 0.f, sq = 0.f, acc[NEXP];
#pragma unroll
    for (int e = 0; e < NEXP; e++) acc[e] = 0.f;
    for (int i = tid; i < DDIM / 4; i += 128) {
        float4 xv = xr[i];
#pragma unroll
        for (int e = 0; e < NEXP; e++) {
            float4 cv = ((const float4*)cent)[e * (DDIM / 4) + i];
            acc[e] += xv.x * cv.x + xv.y * cv.y + xv.z * cv.z + xv.w * cv.w;
        }
        sum += xv.x + xv.y + xv.z + xv.w;
        sq  += xv.x * xv.x + xv.y * xv.y + xv.z * xv.z + xv.w * xv.w;
    }
#pragma unroll
    for (int o = 16; o > 0; o >>= 1) {
        sum += __shfl_xor_sync(0xffffffffu, sum, o);
        sq  += __shfl_xor_sync(0xffffffffu, sq,  o);
#pragma unroll
        for (int e = 0; e < NEXP; e++) acc[e] += __shfl_xor_sync(0xffffffffu, acc[e], o);
    }
    __shared__ float sh[4][NEXP + 2];
    int wid = tid >> 5, lid = tid & 31;
    if (lid == 0) {
        sh[wid][0] = sum; sh[wid][1] = sq;
#pragma unroll
        for (int e = 0; e < NEXP; e++) sh[wid][2 + e] = acc[e];
    }
    __syncthreads();
    if (tid == 0) {
        float s = 0.f, q = 0.f, a[NEXP];
#pragma unroll
        for (int e = 0; e < NEXP; e++) a[e] = 0.f;
        for (int w = 0; w < 4; w++) {
            s += sh[w][0]; q += sh[w][1];
#pragma unroll
            for (int e = 0; e < NEXP; e++) a[e] += sh[w][2 + e];
        }
        float mu  = s * (1.f / DDIM);
        float var = q * (1.f / DDIM) - mu * mu;
        g_mean[t] = mu;
        g_rstd[t] = rsqrtf(var + 1e-5f);
        int be = 0; float bs = a[0];
#pragma unroll
        for (int e = 1; e < NEXP; e++) if (a[e] > bs) { bs = a[e]; be = e; }
        g_eid[t]   = be;
        g_alpha[t] = 1.f / (1.f + expf(-bs));
    }
}

// -------------------- counting sort + m-tile descriptors --------------------
__global__ void sort_kernel() {
    __shared__ int cnt[NEXP], ctr[NEXP];
    int t = threadIdx.x;
    if (t < NEXP) cnt[t] = 0;
    __syncthreads();
    int e = g_eid[t];
    atomicAdd(&cnt[e], 1);
    __syncthreads();
    if (t == 0) {
        int o = 0, nm = 0;
        for (int k = 0; k < NEXP; k++) {
            ctr[k] = o;
            int c = cnt[k];
            for (int i = 0; i < c; i += 128) {
                g_mt_e[nm]  = k;
                g_mt_r0[nm] = o + i;
                g_mt_r1[nm] = o + ((i + 128 < c) ? (i + 128) : c);
                nm++;
            }
            o += c;
        }
        g_num_mt = nm;
    }
    __syncthreads();
    int pos = atomicAdd(&ctr[e], 1);
    g_tok[pos] = t;
    g_eid_s[pos] = e;
    g_alpha_s[pos] = g_alpha[t];
}

// -------------------- LN scatter (fp16-packed, word-permuted) ----------------
__global__ void ln_kernel(const float* __restrict__ x, const float* __restrict__ gamma,
                          const float* __restrict__ beta) {
    int p = blockIdx.x, tid = threadIdx.x;
    int t = g_tok[p], e = g_eid_s[p];
    float mu = g_mean[t], rs = g_rstd[t];
    const float4* xr = (const float4*)(x + (size_t)t * DDIM);
    const float4* gr = (const float4*)(gamma + (size_t)e * DDIM);
    const float4* br = (const float4*)(beta + (size_t)e * DDIM);
    uint32_t* o = g_xn + (size_t)p * (DDIM / 2);
    for (int i = tid; i < DDIM / 4; i += 128) {
        float4 xv = xr[i], gv = gr[i], bv = br[i];
        float v0 = (xv.x - mu) * rs * gv.x + bv.x;
        float v1 = (xv.y - mu) * rs * gv.y + bv.y;
        float v2 = (xv.z - mu) * rs * gv.z + bv.z;
        float v3 = (xv.w - mu) * rs * gv.w + bv.w;
        int w0 = 2 * i, w1 = 2 * i + 1;
        int base = w0 & ~7;
        o[base + pidx(w0 & 7)] = pack_f16(v0, v1);
        o[base + pidx(w1 & 7)] = pack_f16(v2, v3);
    }
}

// -------------------- grouped GEMM (fp16 k16, 64x32 warp tiles, 256 thr) --
// A fp16-packed permuted words (g_xn / g_H); W raw fp32 [E][N][K], cvt in-kernel.
// MODE 1: g_H = relu(A W^T + b), fp16-packed permuted store
// MODE 2: g_part[z] = partial(A W^T) over K chunk z (fp32)
template<int KCHUNK, int KFULL, int NDIM, int MODE>
__global__ void __launch_bounds__(CTA_THREADS, 2) gemm_mma(
    const uint32_t* __restrict__ A, const float* __restrict__ W,
    const float* __restrict__ bias, void* __restrict__ outv)
{
    int mt = blockIdx.y;
    if (mt >= g_num_mt) return;
    int e = g_mt_e[mt], row0 = g_mt_r0[mt], row1 = g_mt_r1[mt];
    int n0 = blockIdx.x * 128;
    int bz = blockIdx.z;
    const int KW = KFULL / 2;            // A row stride in words
    int k0w = bz * (KCHUNK / 2);

    extern __shared__ float sh[];
    uint32_t sA, sB;
    {
        uint32_t base;
        asm("{ .reg .u64 t; cvta.to.shared.u64 t, %1; cvt.u32.u64 %0, t; }"
            : "=r"(base) : "l"(sh));
        sA = base;
        sB = base + STAGES * (STAGE_A_WORDS * 4);
    }
    const uint32_t* shA = (const uint32_t*)sh;
    const float* shB = sh + STAGES * STAGE_A_WORDS;   // B floats after A words

    int tid = threadIdx.x;
    int lane = tid & 31, wid = tid >> 5;      // 8 warps
    int wm = wid >> 2, wn = wid & 3;          // 2 x 4 warp grid, 64x32 tiles
    int lg = lane >> 2, lt = lane & 3;

    const int KT = KCHUNK / 32;

    float acc[4][4][4];                        // 64 registers
#pragma unroll
    for (int a = 0; a < 4; a++)
#pragma unroll
        for (int b = 0; b < 4; b++)
#pragma unroll
            for (int c = 0; c < 4; c++) acc[a][b][c] = 0.f;

    const uint32_t* Abase = A + (size_t)row0 * KW + k0w;
    const float*    Wbase = W + ((size_t)e * NDIM + n0) * KFULL + bz * KCHUNK;

    auto load_stage = [&](int it, int s) {
        if (it < KT) {
            int kk0w = it * 16;                 // 32 k = 16 words
            uint32_t dA = sA + s * (STAGE_A_WORDS * 4);
            uint32_t dB = sB + s * (STAGE_B_FLOATS * 4);
            // A: 128 rows x 16 words = 512 16B-chunks
#pragma unroll
            for (int i = 0; i < 2; i++) {
                int chunk = tid + i * CTA_THREADS;
                int r = chunk >> 2, c = chunk & 3;
                cp16(dA + r * (PADA * 4) + c * 16, Abase + (size_t)r * KW + kk0w + c * 4);
            }
            // B: 128 rows x 32 floats = 1024 16B-chunks
#pragma unroll
            for (int i = 0; i < 4; i++) {
                int chunk = tid + i * CTA_THREADS;
                int r = chunk >> 3, c = chunk & 7;
                cp16(dB + r * (ROWPAD * 4) + c * 16,
                     Wbase + (size_t)r * KFULL + it * 32 + c * 4);
            }
        }
        cp_commit();
    };

    load_stage(0, 0);
    load_stage(1, 1);

    for (int it = 0; it < KT; it++) {
        cp_wait1();
        __syncthreads();
        load_stage(it + 2, (it + 2) % STAGES);

        int s = it % STAGES;
        const uint32_t* As = shA + s * STAGE_A_WORDS;
        const float*    Bs = shB + s * STAGE_B_FLOATS;

        // two k16 chunks per 32-k iter
#pragma unroll
        for (int c16 = 0; c16 < 2; c16++) {
            uint32_t afr[4][4];
#pragma unroll
            for (int m = 0; m < 4; m++) {
                // permuted: pair at 2*lt = logical words (lt, lt+4) = a0,a2
                const uint32_t* ap = As + (wm * 64 + m * 16 + lg) * PADA + c16 * 8 + 2 * lt;
                uint2 p0 = *(const uint2*)ap;                 // row lg
                uint2 p1 = *(const uint2*)(ap + 8 * PADA);    // row lg+8
                afr[m][0] = p0.x; afr[m][2] = p0.y;
                afr[m][1] = p1.x; afr[m][3] = p1.y;
            }
#pragma unroll
            for (int n = 0; n < 4; n++) {
                const float* bp = Bs + (wn * 32 + n * 8 + lg) * ROWPAD + c16 * 16 + 2 * lt;
                float2 q0 = *(const float2*)bp;          // k = 2lt, 2lt+1
                float2 q1 = *(const float2*)(bp + 8);    // k = 2lt+8, 2lt+9
                uint32_t bfr[2];
                bfr[0] = pack_f16(q0.x, q0.y);
                bfr[1] = pack_f16(q1.x, q1.y);
#pragma unroll
                for (int m = 0; m < 4; m++)
                    mma_f16(acc[m][n], afr[m], bfr);
            }
        }
    }

    // -------------------- epilogue --------------------
#pragma unroll
    for (int m = 0; m < 4; m++) {
#pragma unroll
        for (int half = 0; half < 2; half++) {
            int r = wm * 64 + m * 16 + half * 8 + lg;
            int p = row0 + r;
            if (p >= row1) continue;
            if (MODE == 1) {
                // relu + bias, fp16-pack, word-permuted store into g_H
                uint32_t* dst = (uint32_t*)outv + (size_t)p * (NDIM / 2) + n0 / 2;
                const float* bs = bias + (size_t)e * NDIM + n0;
#pragma unroll
                for (int n = 0; n < 4; n++) {
                    int col8 = wn * 32 + n * 8;
                    float v0 = fmaxf(acc[m][n][half * 2 + 0] + bs[col8 + 2 * lt],     0.f);
                    float v1 = fmaxf(acc[m][n][half * 2 + 1] + bs[col8 + 2 * lt + 1], 0.f);
                    int lw = (col8 >> 1) + lt;          // local word index 0..63
                    dst[(lw & ~7) + pidx(lw & 7)] = pack_f16(v0, v1);
                }
            } else {
                // raw fp32 partial store into this K-chunk's slab
                float* dst = (float*)outv + ((size_t)bz * ROWS_PAD + p) * NDIM + n0;
#pragma unroll
                for (int n = 0; n < 4; n++) {
                    int col = wn * 32 + n * 8 + 2 * lt;
                    float2 o;
                    o.x = acc[m][n][half * 2 + 0];
                    o.y = acc[m][n][half * 2 + 1];
                    *(float2*)(dst + col) = o;
                }
            }
        }
    }
}

// -------------------- split-K combine + gated residual --------------------
__global__ void combine_kernel(const float* __restrict__ x, const float* __restrict__ b2,
                               float* __restrict__ out) {
    int p = blockIdx.x, tid = threadIdx.x;
    int t = g_tok[p], e = g_eid_s[p];
    float al = g_alpha_s[p];
    const float4* xr = (const float4*)(x + (size_t)t * DDIM);
    const float4* bs = (const float4*)(b2 + (size_t)e * DDIM);
    float4* dst = (float4*)(out + (size_t)t * DDIM);
    for (int i = tid; i < DDIM / 4; i += 128) {
        float4 s = ((const float4*)(g_part + (size_t)p * DDIM))[i];
#pragma unroll
        for (int z = 1; z < KSPLIT; z++) {
            float4 v = ((const float4*)(g_part + ((size_t)z * ROWS_PAD + p) * DDIM))[i];
            s.x += v.x; s.y += v.y; s.z += v.z; s.w += v.w;
        }
        float4 xv = xr[i], bv = bs[i], o;
        o.x = xv.x + al * (s.x + bv.x);
        o.y = xv.y + al * (s.y + bv.y);
        o.z = xv.z + al * (s.z + bv.z);
        o.w = xv.w + al * (s.w + bv.w);
        dst[i] = o;
    }
}

// -------------------- host --------------------
extern "C" void kernel_launch(void* const* d_in, const int* in_sizes, int n_in,
                              void* d_out, int out_size) {
    const float* x     = (const float*)d_in[0];
    const float* cent  = (const float*)d_in[1];
    const float* gamma = (const float*)d_in[2];
    const float* beta  = (const float*)d_in[3];
    const float* W1    = (const float*)d_in[4];
    const float* b1    = (const float*)d_in[5];
    const float* W2    = (const float*)d_in[6];
    const float* b2    = (const float*)d_in[7];
    float* out = (float*)d_out;

    void* pxn = nullptr; void* pH = nullptr; void* ppart = nullptr;
    cudaGetSymbolAddress(&pxn, g_xn);
    cudaGetSymbolAddress(&pH,  g_H);
    cudaGetSymbolAddress(&ppart, g_part);

    cudaFuncSetAttribute((const void*)gemm_mma<DDIM, DDIM, FDIM, 1>,
                         cudaFuncAttributeMaxDynamicSharedMemorySize, SMEM_GEMM);
    cudaFuncSetAttribute((const void*)gemm_mma<FDIM / KSPLIT, FDIM, DDIM, 2>,
                         cudaFuncAttributeMaxDynamicSharedMemorySize, SMEM_GEMM);

    route_kernel<<<TOKS, 128>>>(x, cent);
    sort_kernel<<<1, TOKS>>>();
    ln_kernel<<<TOKS, 128>>>(x, gamma, beta);
    gemm_mma<DDIM, DDIM, FDIM, 1><<<dim3(FDIM / 128, MAX_MT, 1), CTA_THREADS, SMEM_GEMM>>>(
        (const uint32_t*)pxn, W1, b1, pH);
    gemm_mma<FDIM / KSPLIT, FDIM, DDIM, 2><<<dim3(DDIM / 128, MAX_MT, KSPLIT), CTA_THREADS, SMEM_GEMM>>>(
        (const uint32_t*)pH, W2, nullptr, ppart);
    combine_kernel<<<TOKS, 128>>>(x, b2, out);
}

// round 12
// speedup vs baseline: 2.2841x; 1.0166x over previous
#include <cuda_runtime.h>
#include <cstdint>

// ============================================================
// BASE MoE layer (sm_103 plain-target: fp16 m16n8k16 mma.sync, fp32 accum)
// out[t] = x[t] + sigmoid(score)*( relu(LN_e(x) W1e^T + b1e) W2e^T + b2e )
// R12: R11 + convert W to fp16 in the GEMM load path (LDG->cvt->STS,
//      double-buffered B slots, 1-iter register prefetch). B fragment
//      = one LDS.64, no cvt. Same rn rounding -> bit-identical output.
// ============================================================

#define TOKS 1024
#define DDIM 1024
#define FDIM 4096
#define NEXP 8
#define ROWS_PAD 1152
#define MAX_MT 16
#define KSPLIT 4
#define STAGES 3                          // A cp.async stages
#define PADA 24                           // 16 words + 8 pad (conflict-free LDS.64)
#define STAGE_A_WORDS (128 * PADA)        // 3072 words = 12288 B
#define SMEM_GEMM ((STAGES + 2) * STAGE_A_WORDS * 4)   // A*3 + B*2 = 61440 B
#define CTA_THREADS 256

// -------------------- device scratch --------------------
// A operands: packed fp16x2 words, permuted [0,4,1,5,2,6,3,7] per 8-word group
__device__ uint32_t g_xn[ROWS_PAD * DDIM / 2];
__device__ uint32_t g_H [ROWS_PAD * FDIM / 2];
__device__ float    g_part[KSPLIT * ROWS_PAD * DDIM];
__device__ float g_mean[TOKS], g_rstd[TOKS], g_alpha[TOKS];
__device__ float g_alpha_s[TOKS];
__device__ int   g_eid[TOKS], g_eid_s[TOKS], g_tok[TOKS];
__device__ int   g_mt_e[MAX_MT], g_mt_r0[MAX_MT], g_mt_r1[MAX_MT];
__device__ int   g_num_mt;

// -------------------- PTX helpers --------------------
__device__ __forceinline__ void cp16(uint32_t dst, const void* src) {
    asm volatile("cp.async.cg.shared.global [%0], [%1], 16;" :: "r"(dst), "l"(src));
}
__device__ __forceinline__ void cp_commit() {
    asm volatile("cp.async.commit_group;" ::: "memory");
}
__device__ __forceinline__ void cp_wait1() {
    asm volatile("cp.async.wait_group 1;" ::: "memory");
}
// pack (lo, hi) floats -> fp16x2 word (lower 16 bits = lo)
__device__ __forceinline__ uint32_t pack_f16(float lo, float hi) {
    uint32_t r;
    asm("cvt.rn.f16x2.f32 %0, %1, %2;" : "=r"(r) : "f"(hi), "f"(lo));
    return r;
}
__device__ __forceinline__ void mma_f16(float* c, const uint32_t* a, const uint32_t* b) {
    asm volatile(
        "mma.sync.aligned.m16n8k16.row.col.f32.f16.f16.f32 "
        "{%0,%1,%2,%3}, {%4,%5,%6,%7}, {%8,%9}, {%0,%1,%2,%3};"
        : "+f"(c[0]), "+f"(c[1]), "+f"(c[2]), "+f"(c[3])
        : "r"(a[0]), "r"(a[1]), "r"(a[2]), "r"(a[3]), "r"(b[0]), "r"(b[1]));
}
// permuted position of logical word j within its 8-word group: [0,4,1,5,2,6,3,7]
__device__ __forceinline__ int pidx(int j) { return ((j & 3) << 1) | ((j & 4) >> 2); }

// -------------------- routing --------------------
__global__ void route_kernel(const float* __restrict__ x, const float* __restrict__ cent) {
    int t = blockIdx.x, tid = threadIdx.x;
    const float4* xr = (const float4*)(x + (size_t)t * DDIM);
    float sum = 0.f, sq = 0.f, acc[NEXP];
#pragma unroll
    for (int e = 0; e < NEXP; e++) acc[e] = 0.f;
    for (int i = tid; i < DDIM / 4; i += 128) {
        float4 xv = xr[i];
#pragma unroll
        for (int e = 0; e < NEXP; e++) {
            float4 cv = ((const float4*)cent)[e * (DDIM / 4) + i];
            acc[e] += xv.x * cv.x + xv.y * cv.y + xv.z * cv.z + xv.w * cv.w;
        }
        sum += xv.x + xv.y + xv.z + xv.w;
        sq  += xv.x * xv.x + xv.y * xv.y + xv.z * xv.z + xv.w * xv.w;
    }
#pragma unroll
    for (int o = 16; o > 0; o >>= 1) {
        sum += __shfl_xor_sync(0xffffffffu, sum, o);
        sq  += __shfl_xor_sync(0xffffffffu, sq,  o);
#pragma unroll
        for (int e = 0; e < NEXP; e++) acc[e] += __shfl_xor_sync(0xffffffffu, acc[e], o);
    }
    __shared__ float sh[4][NEXP + 2];
    int wid = tid >> 5, lid = tid & 31;
    if (lid == 0) {
        sh[wid][0] = sum; sh[wid][1] = sq;
#pragma unroll
        for (int e = 0; e < NEXP; e++) sh[wid][2 + e] = acc[e];
    }
    __syncthreads();
    if (tid == 0) {
        float s = 0.f, q = 0.f, a[NEXP];
#pragma unroll
        for (int e = 0; e < NEXP; e++) a[e] = 0.f;
        for (int w = 0; w < 4; w++) {
            s += sh[w][0]; q += sh[w][1];
#pragma unroll
            for (int e = 0; e < NEXP; e++) a[e] += sh[w][2 + e];
        }
        float mu  = s * (1.f / DDIM);
        float var = q * (1.f / DDIM) - mu * mu;
        g_mean[t] = mu;
        g_rstd[t] = rsqrtf(var + 1e-5f);
        int be = 0; float bs = a[0];
#pragma unroll
        for (int e = 1; e < NEXP; e++) if (a[e] > bs) { bs = a[e]; be = e; }
        g_eid[t]   = be;
        g_alpha[t] = 1.f / (1.f + expf(-bs));
    }
}

// -------------------- counting sort + m-tile descriptors --------------------
__global__ void sort_kernel() {
    __shared__ int cnt[NEXP], ctr[NEXP];
    int t = threadIdx.x;
    if (t < NEXP) cnt[t] = 0;
    __syncthreads();
    int e = g_eid[t];
    atomicAdd(&cnt[e], 1);
    __syncthreads();
    if (t == 0) {
        int o = 0, nm = 0;
        for (int k = 0; k < NEXP; k++) {
            ctr[k] = o;
            int c = cnt[k];
            for (int i = 0; i < c; i += 128) {
                g_mt_e[nm]  = k;
                g_mt_r0[nm] = o + i;
                g_mt_r1[nm] = o + ((i + 128 < c) ? (i + 128) : c);
                nm++;
            }
            o += c;
        }
        g_num_mt = nm;
    }
    __syncthreads();
    int pos = atomicAdd(&ctr[e], 1);
    g_tok[pos] = t;
    g_eid_s[pos] = e;
    g_alpha_s[pos] = g_alpha[t];
}

// -------------------- LN scatter (fp16-packed, word-permuted) ----------------
__global__ void ln_kernel(const float* __restrict__ x, const float* __restrict__ gamma,
                          const float* __restrict__ beta) {
    int p = blockIdx.x, tid = threadIdx.x;
    int t = g_tok[p], e = g_eid_s[p];
    float mu = g_mean[t], rs = g_rstd[t];
    const float4* xr = (const float4*)(x + (size_t)t * DDIM);
    const float4* gr = (const float4*)(gamma + (size_t)e * DDIM);
    const float4* br = (const float4*)(beta + (size_t)e * DDIM);
    uint32_t* o = g_xn + (size_t)p * (DDIM / 2);
    for (int i = tid; i < DDIM / 4; i += 128) {
        float4 xv = xr[i], gv = gr[i], bv = br[i];
        float v0 = (xv.x - mu) * rs * gv.x + bv.x;
        float v1 = (xv.y - mu) * rs * gv.y + bv.y;
        float v2 = (xv.z - mu) * rs * gv.z + bv.z;
        float v3 = (xv.w - mu) * rs * gv.w + bv.w;
        int w0 = 2 * i, w1 = 2 * i + 1;
        int base = w0 & ~7;
        o[base + pidx(w0 & 7)] = pack_f16(v0, v1);
        o[base + pidx(w1 & 7)] = pack_f16(v2, v3);
    }
}

// -------------------- grouped GEMM (fp16 k16, fp16 B via convert-on-load) --
// A fp16-packed permuted words (g_xn / g_H); W fp32 [E][N][K] converted
// to fp16 in the load path (LDG->cvt->STS). Both A and B smem tiles use
// the permuted 16-word rows with PADA padding.
// MODE 1: g_H = relu(A W^T + b), fp16-packed permuted store
// MODE 2: g_part[z] = partial(A W^T) over K chunk z (fp32)
template<int KCHUNK, int KFULL, int NDIM, int MODE>
__global__ void __launch_bounds__(CTA_THREADS, 2) gemm_mma(
    const uint32_t* __restrict__ A, const float* __restrict__ W,
    const float* __restrict__ bias, void* __restrict__ outv)
{
    int mt = blockIdx.y;
    if (mt >= g_num_mt) return;
    int e = g_mt_e[mt], row0 = g_mt_r0[mt], row1 = g_mt_r1[mt];
    int n0 = blockIdx.x * 128;
    int bz = blockIdx.z;
    const int KW = KFULL / 2;            // A row stride in words
    int k0w = bz * (KCHUNK / 2);

    extern __shared__ uint32_t shw[];
    uint32_t sA;
    asm("{ .reg .u64 t; cvta.to.shared.u64 t, %1; cvt.u32.u64 %0, t; }"
        : "=r"(sA) : "l"(shw));
    const uint32_t* shA = shw;                           // 3 A stages
    uint32_t* shB = shw + STAGES * STAGE_A_WORDS;        // 2 B slots

    int tid = threadIdx.x;
    int lane = tid & 31, wid = tid >> 5;      // 8 warps
    int wm = wid >> 2, wn = wid & 3;          // 2 x 4 warp grid, 64x32 tiles
    int lg = lane >> 2, lt = lane & 3;

    const int KT = KCHUNK / 32;

    float acc[4][4][4];                        // 64 registers
#pragma unroll
    for (int a = 0; a < 4; a++)
#pragma unroll
        for (int b = 0; b < 4; b++)
#pragma unroll
            for (int c = 0; c < 4; c++) acc[a][b][c] = 0.f;

    const uint32_t* Abase = A + (size_t)row0 * KW + k0w;
    const float*    Wbase = W + ((size_t)e * NDIM + n0) * KFULL + bz * KCHUNK;

    // ---- A: cp.async stages (unchanged from R11) ----
    auto load_stageA = [&](int it, int s) {
        if (it < KT) {
            int kk0w = it * 16;
            uint32_t dA = sA + s * (STAGE_A_WORDS * 4);
#pragma unroll
            for (int i = 0; i < 2; i++) {
                int chunk = tid + i * CTA_THREADS;
                int r = chunk >> 2, c = chunk & 3;
                cp16(dA + r * (PADA * 4) + c * 16, Abase + (size_t)r * KW + kk0w + c * 4);
            }
        }
        cp_commit();
    };

    // ---- B: register prefetch + convert + STS ----
    int br = tid >> 1, bh = tid & 1;          // row 0..127, half 0/1
    const float4* Bg = (const float4*)(Wbase + (size_t)br * KFULL + bh * 16);
    const int BSTRIDE4 = KFULL / 4;           // float4 stride per k-iter row
    float4 breg0, breg1, breg2, breg3;

    auto ldgB = [&](int it) {
        if (it < KT) {
            const float4* p = Bg + it * 8;    // it*32 floats = it*8 float4
            breg0 = p[0]; breg1 = p[1]; breg2 = p[2]; breg3 = p[3];
        }
    };
    auto stsB = [&](int it) {
        if (it < KT) {
            uint32_t* d = shB + (it & 1) * STAGE_A_WORDS + br * PADA + bh * 8;
            // pair (w_j, w_{j+4}) at positions (2j, 2j+1)
            uint2 v;
            v.x = pack_f16(breg0.x, breg0.y); v.y = pack_f16(breg2.x, breg2.y);
            *(uint2*)(d + 0) = v;
            v.x = pack_f16(breg0.z, breg0.w); v.y = pack_f16(breg2.z, breg2.w);
            *(uint2*)(d + 2) = v;
            v.x = pack_f16(breg1.x, breg1.y); v.y = pack_f16(breg3.x, breg3.y);
            *(uint2*)(d + 4) = v;
            v.x = pack_f16(breg1.z, breg1.w); v.y = pack_f16(breg3.z, breg3.w);
            *(uint2*)(d + 6) = v;
        }
    };

    // prolog
    ldgB(0);
    stsB(0);
    ldgB(1);
    load_stageA(0, 0);
    load_stageA(1, 1);

    for (int it = 0; it < KT; it++) {
        cp_wait1();
        __syncthreads();          // A stage it ready; B slot it&1 ready; frees slot (it+1)&1

        stsB(it + 1);             // breg holds B(it+1) -> slot (it+1)&1
        ldgB(it + 2);             // prefetch next into regs (covers DRAM latency)
        load_stageA(it + 2, (it + 2) % STAGES);

        const uint32_t* As = shA + (it % STAGES) * STAGE_A_WORDS;
        const uint32_t* Bs = shB + (it & 1) * STAGE_A_WORDS;

#pragma unroll
        for (int c16 = 0; c16 < 2; c16++) {
            uint32_t afr[4][4];
#pragma unroll
            for (int m = 0; m < 4; m++) {
                const uint32_t* ap = As + (wm * 64 + m * 16 + lg) * PADA + c16 * 8 + 2 * lt;
                uint2 p0 = *(const uint2*)ap;                 // row lg
                uint2 p1 = *(const uint2*)(ap + 8 * PADA);    // row lg+8
                afr[m][0] = p0.x; afr[m][2] = p0.y;
                afr[m][1] = p1.x; afr[m][3] = p1.y;
            }
#pragma unroll
            for (int n = 0; n < 4; n++) {
                const uint32_t* bp = Bs + (wn * 32 + n * 8 + lg) * PADA + c16 * 8 + 2 * lt;
                uint2 bw = *(const uint2*)bp;
                uint32_t bfr[2] = { bw.x, bw.y };
#pragma unroll
                for (int m = 0; m < 4; m++)
                    mma_f16(acc[m][n], afr[m], bfr);
            }
        }
    }

    // -------------------- epilogue --------------------
#pragma unroll
    for (int m = 0; m < 4; m++) {
#pragma unroll
        for (int half = 0; half < 2; half++) {
            int r = wm * 64 + m * 16 + half * 8 + lg;
            int p = row0 + r;
            if (p >= row1) continue;
            if (MODE == 1) {
                // relu + bias, fp16-pack, word-permuted store into g_H
                uint32_t* dst = (uint32_t*)outv + (size_t)p * (NDIM / 2) + n0 / 2;
                const float* bs = bias + (size_t)e * NDIM + n0;
#pragma unroll
                for (int n = 0; n < 4; n++) {
                    int col8 = wn * 32 + n * 8;
                    float v0 = fmaxf(acc[m][n][half * 2 + 0] + bs[col8 + 2 * lt],     0.f);
                    float v1 = fmaxf(acc[m][n][half * 2 + 1] + bs[col8 + 2 * lt + 1], 0.f);
                    int lw = (col8 >> 1) + lt;          // local word index 0..63
                    dst[(lw & ~7) + pidx(lw & 7)] = pack_f16(v0, v1);
                }
            } else {
                // raw fp32 partial store into this K-chunk's slab
                float* dst = (float*)outv + ((size_t)bz * ROWS_PAD + p) * NDIM + n0;
#pragma unroll
                for (int n = 0; n < 4; n++) {
                    int col = wn * 32 + n * 8 + 2 * lt;
                    float2 o;
                    o.x = acc[m][n][half * 2 + 0];
                    o.y = acc[m][n][half * 2 + 1];
                    *(float2*)(dst + col) = o;
                }
            }
        }
    }
    (void)BSTRIDE4;
}

// -------------------- split-K combine + gated residual --------------------
__global__ void combine_kernel(const float* __restrict__ x, const float* __restrict__ b2,
                               float* __restrict__ out) {
    int p = blockIdx.x, tid = threadIdx.x;
    int t = g_tok[p], e = g_eid_s[p];
    float al = g_alpha_s[p];
    const float4* xr = (const float4*)(x + (size_t)t * DDIM);
    const float4* bs = (const float4*)(b2 + (size_t)e * DDIM);
    float4* dst = (float4*)(out + (size_t)t * DDIM);
    for (int i = tid; i < DDIM / 4; i += 128) {
        float4 s = ((const float4*)(g_part + (size_t)p * DDIM))[i];
#pragma unroll
        for (int z = 1; z < KSPLIT; z++) {
            float4 v = ((const float4*)(g_part + ((size_t)z * ROWS_PAD + p) * DDIM))[i];
            s.x += v.x; s.y += v.y; s.z += v.z; s.w += v.w;
        }
        float4 xv = xr[i], bv = bs[i], o;
        o.x = xv.x + al * (s.x + bv.x);
        o.y = xv.y + al * (s.y + bv.y);
        o.z = xv.z + al * (s.z + bv.z);
        o.w = xv.w + al * (s.w + bv.w);
        dst[i] = o;
    }
}

// -------------------- host --------------------
extern "C" void kernel_launch(void* const* d_in, const int* in_sizes, int n_in,
                              void* d_out, int out_size) {
    const float* x     = (const float*)d_in[0];
    const float* cent  = (const float*)d_in[1];
    const float* gamma = (const float*)d_in[2];
    const float* beta  = (const float*)d_in[3];
    const float* W1    = (const float*)d_in[4];
    const float* b1    = (const float*)d_in[5];
    const float* W2    = (const float*)d_in[6];
    const float* b2    = (const float*)d_in[7];
    float* out = (float*)d_out;

    void* pxn = nullptr; void* pH = nullptr; void* ppart = nullptr;
    cudaGetSymbolAddress(&pxn, g_xn);
    cudaGetSymbolAddress(&pH,  g_H);
    cudaGetSymbolAddress(&ppart, g_part);

    cudaFuncSetAttribute((const void*)gemm_mma<DDIM, DDIM, FDIM, 1>,
                         cudaFuncAttributeMaxDynamicSharedMemorySize, SMEM_GEMM);
    cudaFuncSetAttribute((const void*)gemm_mma<FDIM / KSPLIT, FDIM, DDIM, 2>,
                         cudaFuncAttributeMaxDynamicSharedMemorySize, SMEM_GEMM);

    route_kernel<<<TOKS, 128>>>(x, cent);
    sort_kernel<<<1, TOKS>>>();
    ln_kernel<<<TOKS, 128>>>(x, gamma, beta);
    gemm_mma<DDIM, DDIM, FDIM, 1><<<dim3(FDIM / 128, MAX_MT, 1), CTA_THREADS, SMEM_GEMM>>>(
        (const uint32_t*)pxn, W1, b1, pH);
    gemm_mma<FDIM / KSPLIT, FDIM, DDIM, 2><<<dim3(DDIM / 128, MAX_MT, KSPLIT), CTA_THREADS, SMEM_GEMM>>>(
        (const uint32_t*)pH, W2, nullptr, ppart);
    combine_kernel<<<TOKS, 128>>>(x, b2, out);
}

// round 13
// speedup vs baseline: 2.7905x; 1.2217x over previous
#include <cuda_runtime.h>
#include <cstdint>

// ============================================================
// BASE MoE layer (sm_103 plain-target: fp16 m16n8k16 mma.sync, fp32 accum)
// out[t] = x[t] + sigmoid(score)*( relu(LN_e(x) W1e^T + b1e) W2e^T + b2e )
// R13: HMMA issue floor => time ~ MMA instruction count. Cut waste:
//      64-row m-tiles (padding 1.6x -> ~1.15x) + 64x256 CTA tiles
//      (~288 CTAs = one full wave). 2-stage compute-then-load pipeline.
// ============================================================

#define TOKS 1024
#define DDIM 1024
#define FDIM 4096
#define NEXP 8
#define ROWS_PAD 1152
#define MAX_MT 32                         // 64-row m-tiles: <= 8 + 1024/64 = 24
#define KSPLIT 4
#define PADA 24                           // A: 16 words + 8 pad
#define ROWPAD 36                         // B: 32 floats + 4 pad
#define STAGE_A_WORDS (64 * PADA)         // 1536 words = 6144 B
#define STAGE_B_FLOATS (256 * ROWPAD)     // 9216 floats = 36864 B
#define SMEM_GEMM (2 * (STAGE_A_WORDS * 4 + STAGE_B_FLOATS * 4))   // 86016 B
#define CTA_THREADS 256

// -------------------- device scratch --------------------
// A operands: packed fp16x2 words, permuted [0,4,1,5,2,6,3,7] per 8-word group
__device__ uint32_t g_xn[ROWS_PAD * DDIM / 2];
__device__ uint32_t g_H [ROWS_PAD * FDIM / 2];
__device__ float    g_part[KSPLIT * ROWS_PAD * DDIM];
__device__ float g_mean[TOKS], g_rstd[TOKS], g_alpha[TOKS];
__device__ float g_alpha_s[TOKS];
__device__ int   g_eid[TOKS], g_eid_s[TOKS], g_tok[TOKS];
__device__ int   g_mt_e[MAX_MT], g_mt_r0[MAX_MT], g_mt_r1[MAX_MT];
__device__ int   g_num_mt;

// -------------------- PTX helpers --------------------
__device__ __forceinline__ void cp16(uint32_t dst, const void* src) {
    asm volatile("cp.async.cg.shared.global [%0], [%1], 16;" :: "r"(dst), "l"(src));
}
__device__ __forceinline__ void cp_commit() {
    asm volatile("cp.async.commit_group;" ::: "memory");
}
__device__ __forceinline__ void cp_wait1() {
    asm volatile("cp.async.wait_group 1;" ::: "memory");
}
// pack (lo, hi) floats -> fp16x2 word (lower 16 bits = lo)
__device__ __forceinline__ uint32_t pack_f16(float lo, float hi) {
    uint32_t r;
    asm("cvt.rn.f16x2.f32 %0, %1, %2;" : "=r"(r) : "f"(hi), "f"(lo));
    return r;
}
__device__ __forceinline__ void mma_f16(float* c, const uint32_t* a, const uint32_t* b) {
    asm volatile(
        "mma.sync.aligned.m16n8k16.row.col.f32.f16.f16.f32 "
        "{%0,%1,%2,%3}, {%4,%5,%6,%7}, {%8,%9}, {%0,%1,%2,%3};"
        : "+f"(c[0]), "+f"(c[1]), "+f"(c[2]), "+f"(c[3])
        : "r"(a[0]), "r"(a[1]), "r"(a[2]), "r"(a[3]), "r"(b[0]), "r"(b[1]));
}
// permuted position of logical word j within its 8-word group: [0,4,1,5,2,6,3,7]
__device__ __forceinline__ int pidx(int j) { return ((j & 3) << 1) | ((j & 4) >> 2); }

// -------------------- routing --------------------
__global__ void route_kernel(const float* __restrict__ x, const float* __restrict__ cent) {
    int t = blockIdx.x, tid = threadIdx.x;
    const float4* xr = (const float4*)(x + (size_t)t * DDIM);
    float sum = 0.f, sq = 0.f, acc[NEXP];
#pragma unroll
    for (int e = 0; e < NEXP; e++) acc[e] = 0.f;
    for (int i = tid; i < DDIM / 4; i += 128) {
        float4 xv = xr[i];
#pragma unroll
        for (int e = 0; e < NEXP; e++) {
            float4 cv = ((const float4*)cent)[e * (DDIM / 4) + i];
            acc[e] += xv.x * cv.x + xv.y * cv.y + xv.z * cv.z + xv.w * cv.w;
        }
        sum += xv.x + xv.y + xv.z + xv.w;
        sq  += xv.x * xv.x + xv.y * xv.y + xv.z * xv.z + xv.w * xv.w;
    }
#pragma unroll
    for (int o = 16; o > 0; o >>= 1) {
        sum += __shfl_xor_sync(0xffffffffu, sum, o);
        sq  += __shfl_xor_sync(0xffffffffu, sq,  o);
#pragma unroll
        for (int e = 0; e < NEXP; e++) acc[e] += __shfl_xor_sync(0xffffffffu, acc[e], o);
    }
    __shared__ float sh[4][NEXP + 2];
    int wid = tid >> 5, lid = tid & 31;
    if (lid == 0) {
        sh[wid][0] = sum; sh[wid][1] = sq;
#pragma unroll
        for (int e = 0; e < NEXP; e++) sh[wid][2 + e] = acc[e];
    }
    __syncthreads();
    if (tid == 0) {
        float s = 0.f, q = 0.f, a[NEXP];
#pragma unroll
        for (int e = 0; e < NEXP; e++) a[e] = 0.f;
        for (int w = 0; w < 4; w++) {
            s += sh[w][0]; q += sh[w][1];
#pragma unroll
            for (int e = 0; e < NEXP; e++) a[e] += sh[w][2 + e];
        }
        float mu  = s * (1.f / DDIM);
        float var = q * (1.f / DDIM) - mu * mu;
        g_mean[t] = mu;
        g_rstd[t] = rsqrtf(var + 1e-5f);
        int be = 0; float bs = a[0];
#pragma unroll
        for (int e = 1; e < NEXP; e++) if (a[e] > bs) { bs = a[e]; be = e; }
        g_eid[t]   = be;
        g_alpha[t] = 1.f / (1.f + expf(-bs));
    }
}

// -------------------- counting sort + 64-row m-tile descriptors -------------
__global__ void sort_kernel() {
    __shared__ int cnt[NEXP], ctr[NEXP];
    int t = threadIdx.x;
    if (t < NEXP) cnt[t] = 0;
    __syncthreads();
    int e = g_eid[t];
    atomicAdd(&cnt[e], 1);
    __syncthreads();
    if (t == 0) {
        int o = 0, nm = 0;
        for (int k = 0; k < NEXP; k++) {
            ctr[k] = o;
            int c = cnt[k];
            for (int i = 0; i < c; i += 64) {
                g_mt_e[nm]  = k;
                g_mt_r0[nm] = o + i;
                g_mt_r1[nm] = o + ((i + 64 < c) ? (i + 64) : c);
                nm++;
            }
            o += c;
        }
        g_num_mt = nm;
    }
    __syncthreads();
    int pos = atomicAdd(&ctr[e], 1);
    g_tok[pos] = t;
    g_eid_s[pos] = e;
    g_alpha_s[pos] = g_alpha[t];
}

// -------------------- LN scatter (fp16-packed, word-permuted) ----------------
__global__ void ln_kernel(const float* __restrict__ x, const float* __restrict__ gamma,
                          const float* __restrict__ beta) {
    int p = blockIdx.x, tid = threadIdx.x;
    int t = g_tok[p], e = g_eid_s[p];
    float mu = g_mean[t], rs = g_rstd[t];
    const float4* xr = (const float4*)(x + (size_t)t * DDIM);
    const float4* gr = (const float4*)(gamma + (size_t)e * DDIM);
    const float4* br = (const float4*)(beta + (size_t)e * DDIM);
    uint32_t* o = g_xn + (size_t)p * (DDIM / 2);
    for (int i = tid; i < DDIM / 4; i += 128) {
        float4 xv = xr[i], gv = gr[i], bv = br[i];
        float v0 = (xv.x - mu) * rs * gv.x + bv.x;
        float v1 = (xv.y - mu) * rs * gv.y + bv.y;
        float v2 = (xv.z - mu) * rs * gv.z + bv.z;
        float v3 = (xv.w - mu) * rs * gv.w + bv.w;
        int w0 = 2 * i, w1 = 2 * i + 1;
        int base = w0 & ~7;
        o[base + pidx(w0 & 7)] = pack_f16(v0, v1);
        o[base + pidx(w1 & 7)] = pack_f16(v2, v3);
    }
}

// -------------------- grouped GEMM (fp16 k16, 64x256 CTA, 64x32 warps) ----
// A fp16-packed permuted words (g_xn / g_H); W raw fp32 [E][N][K], cvt at frag.
// MODE 1: g_H = relu(A W^T + b), fp16-packed permuted store
// MODE 2: g_part[z] = partial(A W^T) over K chunk z (fp32)
template<int KCHUNK, int KFULL, int NDIM, int MODE>
__global__ void __launch_bounds__(CTA_THREADS, 2) gemm_mma(
    const uint32_t* __restrict__ A, const float* __restrict__ W,
    const float* __restrict__ bias, void* __restrict__ outv)
{
    int mt = blockIdx.y;
    if (mt >= g_num_mt) return;
    int e = g_mt_e[mt], row0 = g_mt_r0[mt], row1 = g_mt_r1[mt];
    int n0 = blockIdx.x * 256;
    int bz = blockIdx.z;
    const int KW = KFULL / 2;            // A row stride in words
    int k0w = bz * (KCHUNK / 2);

    extern __shared__ uint32_t shw[];
    uint32_t sA, sB;
    asm("{ .reg .u64 t; cvta.to.shared.u64 t, %1; cvt.u32.u64 %0, t; }"
        : "=r"(sA) : "l"(shw));
    sB = sA + 2 * STAGE_A_WORDS * 4;
    const uint32_t* shA = shw;
    const float* shB = (const float*)(shw + 2 * STAGE_A_WORDS);

    int tid = threadIdx.x;
    int lane = tid & 31, wid = tid >> 5;      // 8 warps, 1 x 8 grid
    int wn = wid;                             // warp tile 64 x 32 at col wn*32
    int lg = lane >> 2, lt = lane & 3;

    const int KT = KCHUNK / 32;

    float acc[4][4][4];                        // 64 registers
#pragma unroll
    for (int a = 0; a < 4; a++)
#pragma unroll
        for (int b = 0; b < 4; b++)
#pragma unroll
            for (int c = 0; c < 4; c++) acc[a][b][c] = 0.f;

    const uint32_t* Abase = A + (size_t)row0 * KW + k0w;
    const float*    Wbase = W + ((size_t)e * NDIM + n0) * KFULL + bz * KCHUNK;

    auto load_stage = [&](int it, int s) {
        if (it < KT) {
            int kk0w = it * 16;
            uint32_t dA = sA + s * (STAGE_A_WORDS * 4);
            uint32_t dB = sB + s * (STAGE_B_FLOATS * 4);
            // A: 64 rows x 16 words = 256 16B-chunks, 1 per thread
            {
                int r = tid >> 2, c = tid & 3;
                cp16(dA + r * (PADA * 4) + c * 16, Abase + (size_t)r * KW + kk0w + c * 4);
            }
            // B: 256 rows x 32 floats = 2048 16B-chunks, 8 per thread
#pragma unroll
            for (int i = 0; i < 8; i++) {
                int chunk = tid + i * CTA_THREADS;
                int r = chunk >> 3, c = chunk & 7;
                cp16(dB + r * (ROWPAD * 4) + c * 16,
                     Wbase + (size_t)r * KFULL + it * 32 + c * 4);
            }
        }
        cp_commit();
    };

    load_stage(0, 0);
    load_stage(1, 1);

    for (int it = 0; it < KT; it++) {
        cp_wait1();            // stage it fully resident
        __syncthreads();

        int s = it & 1;
        const uint32_t* As = shA + s * STAGE_A_WORDS;
        const float*    Bs = shB + s * STAGE_B_FLOATS;

#pragma unroll
        for (int c16 = 0; c16 < 2; c16++) {
            uint32_t afr[4][4];
#pragma unroll
            for (int m = 0; m < 4; m++) {
                // permuted: pair at 2*lt = logical words (lt, lt+4) = a0,a2
                const uint32_t* ap = As + (m * 16 + lg) * PADA + c16 * 8 + 2 * lt;
                uint2 p0 = *(const uint2*)ap;                 // row lg
                uint2 p1 = *(const uint2*)(ap + 8 * PADA);    // row lg+8
                afr[m][0] = p0.x; afr[m][2] = p0.y;
                afr[m][1] = p1.x; afr[m][3] = p1.y;
            }
#pragma unroll
            for (int n = 0; n < 4; n++) {
                const float* bp = Bs + (wn * 32 + n * 8 + lg) * ROWPAD + c16 * 16 + 2 * lt;
                float2 q0 = *(const float2*)bp;          // k = 2lt, 2lt+1
                float2 q1 = *(const float2*)(bp + 8);    // k = 2lt+8, 2lt+9
                uint32_t bfr[2];
                bfr[0] = pack_f16(q0.x, q0.y);
                bfr[1] = pack_f16(q1.x, q1.y);
#pragma unroll
                for (int m = 0; m < 4; m++)
                    mma_f16(acc[m][n], afr[m], bfr);
            }
        }

        __syncthreads();        // all warps done reading slot s
        load_stage(it + 2, s);  // refill consumed slot
    }

    // -------------------- epilogue --------------------
#pragma unroll
    for (int m = 0; m < 4; m++) {
#pragma unroll
        for (int half = 0; half < 2; half++) {
            int r = m * 16 + half * 8 + lg;
            int p = row0 + r;
            if (p >= row1) continue;
            if (MODE == 1) {
                // relu + bias, fp16-pack, word-permuted store into g_H
                uint32_t* dst = (uint32_t*)outv + (size_t)p * (NDIM / 2) + n0 / 2;
                const float* bs = bias + (size_t)e * NDIM + n0;
#pragma unroll
                for (int n = 0; n < 4; n++) {
                    int col8 = wn * 32 + n * 8;
                    float v0 = fmaxf(acc[m][n][half * 2 + 0] + bs[col8 + 2 * lt],     0.f);
                    float v1 = fmaxf(acc[m][n][half * 2 + 1] + bs[col8 + 2 * lt + 1], 0.f);
                    int lw = (col8 >> 1) + lt;          // local word index 0..127
                    dst[(lw & ~7) + pidx(lw & 7)] = pack_f16(v0, v1);
                }
            } else {
                // raw fp32 partial store into this K-chunk's slab
                float* dst = (float*)outv + ((size_t)bz * ROWS_PAD + p) * NDIM + n0;
#pragma unroll
                for (int n = 0; n < 4; n++) {
                    int col = wn * 32 + n * 8 + 2 * lt;
                    float2 o;
                    o.x = acc[m][n][half * 2 + 0];
                    o.y = acc[m][n][half * 2 + 1];
                    *(float2*)(dst + col) = o;
                }
            }
        }
    }
}

// -------------------- split-K combine + gated residual --------------------
__global__ void combine_kernel(const float* __restrict__ x, const float* __restrict__ b2,
                               float* __restrict__ out) {
    int p = blockIdx.x, tid = threadIdx.x;
    int t = g_tok[p], e = g_eid_s[p];
    float al = g_alpha_s[p];
    const float4* xr = (const float4*)(x + (size_t)t * DDIM);
    const float4* bs = (const float4*)(b2 + (size_t)e * DDIM);
    float4* dst = (float4*)(out + (size_t)t * DDIM);
    for (int i = tid; i < DDIM / 4; i += 128) {
        float4 s = ((const float4*)(g_part + (size_t)p * DDIM))[i];
#pragma unroll
        for (int z = 1; z < KSPLIT; z++) {
            float4 v = ((const float4*)(g_part + ((size_t)z * ROWS_PAD + p) * DDIM))[i];
            s.x += v.x; s.y += v.y; s.z += v.z; s.w += v.w;
        }
        float4 xv = xr[i], bv = bs[i], o;
        o.x = xv.x + al * (s.x + bv.x);
        o.y = xv.y + al * (s.y + bv.y);
        o.z = xv.z + al * (s.z + bv.z);
        o.w = xv.w + al * (s.w + bv.w);
        dst[i] = o;
    }
}

// -------------------- host --------------------
extern "C" void kernel_launch(void* const* d_in, const int* in_sizes, int n_in,
                              void* d_out, int out_size) {
    const float* x     = (const float*)d_in[0];
    const float* cent  = (const float*)d_in[1];
    const float* gamma = (const float*)d_in[2];
    const float* beta  = (const float*)d_in[3];
    const float* W1    = (const float*)d_in[4];
    const float* b1    = (const float*)d_in[5];
    const float* W2    = (const float*)d_in[6];
    const float* b2    = (const float*)d_in[7];
    float* out = (float*)d_out;

    void* pxn = nullptr; void* pH = nullptr; void* ppart = nullptr;
    cudaGetSymbolAddress(&pxn, g_xn);
    cudaGetSymbolAddress(&pH,  g_H);
    cudaGetSymbolAddress(&ppart, g_part);

    cudaFuncSetAttribute((const void*)gemm_mma<DDIM, DDIM, FDIM, 1>,
                         cudaFuncAttributeMaxDynamicSharedMemorySize, SMEM_GEMM);
    cudaFuncSetAttribute((const void*)gemm_mma<FDIM / KSPLIT, FDIM, DDIM, 2>,
                         cudaFuncAttributeMaxDynamicSharedMemorySize, SMEM_GEMM);

    route_kernel<<<TOKS, 128>>>(x, cent);
    sort_kernel<<<1, TOKS>>>();
    ln_kernel<<<TOKS, 128>>>(x, gamma, beta);
    gemm_mma<DDIM, DDIM, FDIM, 1><<<dim3(FDIM / 256, MAX_MT, 1), CTA_THREADS, SMEM_GEMM>>>(
        (const uint32_t*)pxn, W1, b1, pH);
    gemm_mma<FDIM / KSPLIT, FDIM, DDIM, 2><<<dim3(DDIM / 256, MAX_MT, KSPLIT), CTA_THREADS, SMEM_GEMM>>>(
        (const uint32_t*)pH, W2, nullptr, ppart);
    combine_kernel<<<TOKS, 128>>>(x, b2, out);
}